// round 3
// baseline (speedup 1.0000x reference)
#include <cuda_runtime.h>
#include <math.h>

// out = -mean_b log(y[b, argmax(target_b)] + 1e-8)
//       + sum_{b,c} wtab[popc(t_b ^ c)] * y[b,c] / (B*N)
// N = 1024 (10 bits), wtab[0]=0, wtab[p]=6^p (exact in fp32).

#define NCLS   1024
#define SMS    152        // GB300 SM count
#define CPS    3          // CTAs per SM at 80-85 regs, 256 thr
#define BLOCKS (SMS * CPS)
#define TPB    256
#define WPB    (TPB / 32)

__device__ double   g_ce = 0.0;
__device__ double   g_pt = 0.0;
__device__ unsigned g_count = 0;

__global__ __launch_bounds__(TPB, CPS)
void ce_pt_kernel(const float* __restrict__ y, const float* __restrict__ tgt,
                  float* __restrict__ out, int B) {
    __shared__ float  wtab[16];
    __shared__ double s_ce[WPB], s_pt[WPB];

    const int tid  = threadIdx.x;
    const int lane = tid & 31;
    const int wid  = tid >> 5;

    if (tid < 11) {
        float w = 1.0f;
        for (int i = 0; i < tid; i++) w *= 6.0f;   // exact: 6^10 < 2^26
        wtab[tid] = (tid == 0) ? 0.0f : w;
    }
    __syncthreads();

    const int gw = blockIdx.x * WPB + wid;
    const int nw = gridDim.x * WPB;

    float  acc_pt = 0.0f;   // per-lane partial across rows
    double acc_ce = 0.0;    // only the lane owning t contributes per row

    for (int r = gw; r < B; r += nw) {
        const float4* trow = (const float4*)(tgt + (size_t)r * NCLS);
        const float4* yrow = (const float4*)(y   + (size_t)r * NCLS);

        // ---- preload both rows, streaming (evict-first): 16 LDG.128 in flight ----
        float4 tv[8], yv[8];
        #pragma unroll
        for (int it = 0; it < 8; it++) {
            tv[it] = __ldcs(&trow[it * 32 + lane]);
            yv[it] = __ldcs(&yrow[it * 32 + lane]);
        }

        // ---- argmax over target (first-max tie-break) ----
        float bv = -1.0f;
        int   bi = 0;
        #pragma unroll
        for (int it = 0; it < 8; it++) {
            int c = (it * 32 + lane) * 4;
            if (tv[it].x > bv) { bv = tv[it].x; bi = c;     }
            if (tv[it].y > bv) { bv = tv[it].y; bi = c + 1; }
            if (tv[it].z > bv) { bv = tv[it].z; bi = c + 2; }
            if (tv[it].w > bv) { bv = tv[it].w; bi = c + 3; }
        }
        #pragma unroll
        for (int off = 16; off; off >>= 1) {
            float ov = __shfl_xor_sync(0xFFFFFFFFu, bv, off);
            int   oi = __shfl_xor_sync(0xFFFFFFFFu, bi, off);
            if (ov > bv || (ov == bv && oi < bi)) { bv = ov; bi = oi; }
        }
        const int t = bi;   // identical in all lanes

        // ---- weighted sum from registers ----
        float pt = 0.0f;
        #pragma unroll
        for (int it = 0; it < 8; it++) {
            int c = (it * 32 + lane) * 4;
            pt = fmaf(wtab[__popc(t ^  c     )], yv[it].x, pt);
            pt = fmaf(wtab[__popc(t ^ (c + 1))], yv[it].y, pt);
            pt = fmaf(wtab[__popc(t ^ (c + 2))], yv[it].z, pt);
            pt = fmaf(wtab[__popc(t ^ (c + 3))], yv[it].w, pt);
        }
        acc_pt += pt;

        // ---- CE term: extract y[t] from the owning lane's registers ----
        if (lane == ((t >> 2) & 31)) {
            const int itq = t >> 7;
            const int cq  = t & 3;
            float4 v = yv[0];
            #pragma unroll
            for (int it = 1; it < 8; it++) if (it == itq) v = yv[it];
            float yt = (cq == 0) ? v.x : (cq == 1) ? v.y : (cq == 2) ? v.z : v.w;
            acc_ce += (double)logf(yt + 1e-8f);
        }
    }

    // ---- warp reduce (once, after all rows) ----
    double dpt = (double)acc_pt;
    #pragma unroll
    for (int off = 16; off; off >>= 1) {
        dpt    += __shfl_xor_sync(0xFFFFFFFFu, dpt,    off);
        acc_ce += __shfl_xor_sync(0xFFFFFFFFu, acc_ce, off);
    }
    if (lane == 0) { s_ce[wid] = acc_ce; s_pt[wid] = dpt; }
    __syncthreads();

    // ---- block reduce + fenced last-block finish ----
    if (tid == 0) {
        double bce = 0.0, bpt = 0.0;
        #pragma unroll
        for (int i = 0; i < WPB; i++) { bce += s_ce[i]; bpt += s_pt[i]; }
        atomicAdd(&g_ce, bce);
        atomicAdd(&g_pt, bpt);
        __threadfence();
        unsigned old = atomicAdd(&g_count, 1u);
        if (old == gridDim.x - 1) {
            // read through L2 (atomics bypass L1; plain LDG could hit stale L1)
            double CE = atomicAdd(&g_ce, 0.0);
            double PT = atomicAdd(&g_pt, 0.0);
            out[0] = (float)(-CE / (double)B + PT / ((double)B * (double)NCLS));
            // reset for next graph replay (no other block touches these now)
            g_ce = 0.0;
            g_pt = 0.0;
            g_count = 0u;
        }
    }
}

extern "C" void kernel_launch(void* const* d_in, const int* in_sizes, int n_in,
                              void* d_out, int out_size) {
    const float* y_true = (const float*)d_in[0];
    const float* target = (const float*)d_in[1];
    const int B = in_sizes[0] / NCLS;

    ce_pt_kernel<<<BLOCKS, TPB>>>(y_true, target, (float*)d_out, B);
}

// round 4
// speedup vs baseline: 1.0252x; 1.0252x over previous
#include <cuda_runtime.h>
#include <math.h>

// out = -mean_b log(y[b, argmax(target_b)] + 1e-8)
//       + sum_{b,c} wtab[popc(t_b ^ c)] * y[b,c] / (B*N)
// N = 1024 (10 bits), wtab[0]=0, wtab[p]=6^p (exact in fp32).

#define NCLS   1024
#define SMS    152
#define CPS    3
#define BLOCKS (SMS * CPS)
#define TPB    256
#define WPB    (TPB / 32)

__device__ double   g_ce = 0.0;
__device__ double   g_pt = 0.0;
__device__ unsigned g_count = 0;

__global__ __launch_bounds__(TPB, CPS)
void ce_pt_kernel(const float* __restrict__ y, const float* __restrict__ tgt,
                  float* __restrict__ out, int B) {
    __shared__ float  wtab[16];
    __shared__ double s_ce[WPB], s_pt[WPB];

    const int tid  = threadIdx.x;
    const int lane = tid & 31;
    const int wid  = tid >> 5;

    if (tid < 11) {
        float w = 1.0f;
        for (int i = 0; i < tid; i++) w *= 6.0f;   // exact: 6^10 < 2^26
        wtab[tid] = (tid == 0) ? 0.0f : w;
    }
    __syncthreads();

    const int gw = blockIdx.x * WPB + wid;
    const int nw = gridDim.x * WPB;

    float  acc_pt = 0.0f;   // per-lane partial across rows
    double acc_ce = 0.0;    // only the lane owning t contributes per row

    for (int r = gw; r < B; r += nw) {
        const float4* trow = (const float4*)(tgt + (size_t)r * NCLS);
        const float4* yrow = (const float4*)(y   + (size_t)r * NCLS);

        // ---- preload both rows: 16 LDG.128 in flight ----
        float4 tv[8], yv[8];
        #pragma unroll
        for (int it = 0; it < 8; it++) {
            tv[it] = __ldcs(&trow[it * 32 + lane]);
            yv[it] = __ldcs(&yrow[it * 32 + lane]);
        }

        // ---- argmax via packed u64 key: (fbits<<32) | (NCLS-1-idx) ----
        // values are positive (uniform[0,1)) -> IEEE bits monotonic in value;
        // complemented index makes max-key pick the FIRST max on ties.
        unsigned long long bk = 0ull;
        #pragma unroll
        for (int it = 0; it < 8; it++) {
            int c = (it * 32 + lane) * 4;
            unsigned long long k;
            k = ((unsigned long long)__float_as_uint(tv[it].x) << 32) | (unsigned)(NCLS - 1 - c);
            if (k > bk) bk = k;
            k = ((unsigned long long)__float_as_uint(tv[it].y) << 32) | (unsigned)(NCLS - 2 - c);
            if (k > bk) bk = k;
            k = ((unsigned long long)__float_as_uint(tv[it].z) << 32) | (unsigned)(NCLS - 3 - c);
            if (k > bk) bk = k;
            k = ((unsigned long long)__float_as_uint(tv[it].w) << 32) | (unsigned)(NCLS - 4 - c);
            if (k > bk) bk = k;
        }
        #pragma unroll
        for (int off = 16; off; off >>= 1) {
            unsigned long long ok = __shfl_xor_sync(0xFFFFFFFFu, bk, off);
            if (ok > bk) bk = ok;
        }
        const int t = NCLS - 1 - (int)(bk & 0xFFFFFFFFu);   // identical in all lanes

        // ---- weighted sum: factored popcount + 4-way accumulator ILP ----
        const int tb = t >> 2;      // high 8 bits of t
        const int tl = t & 3;       // low 2 bits
        const int d0 = __popc(tl ^ 0), d1 = __popc(tl ^ 1);
        const int d2 = __popc(tl ^ 2), d3 = __popc(tl ^ 3);

        float p0 = 0.0f, p1 = 0.0f, p2 = 0.0f, p3 = 0.0f;
        #pragma unroll
        for (int it = 0; it < 8; it++) {
            const int cb = it * 32 + lane;          // float4 group index = c>>2
            const int pb = __popc(tb ^ cb);
            p0 = fmaf(wtab[pb + d0], yv[it].x, p0);
            p1 = fmaf(wtab[pb + d1], yv[it].y, p1);
            p2 = fmaf(wtab[pb + d2], yv[it].z, p2);
            p3 = fmaf(wtab[pb + d3], yv[it].w, p3);
        }
        acc_pt += (p0 + p1) + (p2 + p3);

        // ---- CE term: extract y[t] from the owning lane's registers ----
        if (lane == ((t >> 2) & 31)) {
            const int itq = t >> 7;
            const int cq  = t & 3;
            float4 v = yv[0];
            #pragma unroll
            for (int it = 1; it < 8; it++) if (it == itq) v = yv[it];
            float yt = (cq == 0) ? v.x : (cq == 1) ? v.y : (cq == 2) ? v.z : v.w;
            acc_ce += (double)logf(yt + 1e-8f);
        }
    }

    // ---- warp reduce (once, after all rows) ----
    double dpt = (double)acc_pt;
    #pragma unroll
    for (int off = 16; off; off >>= 1) {
        dpt    += __shfl_xor_sync(0xFFFFFFFFu, dpt,    off);
        acc_ce += __shfl_xor_sync(0xFFFFFFFFu, acc_ce, off);
    }
    if (lane == 0) { s_ce[wid] = acc_ce; s_pt[wid] = dpt; }
    __syncthreads();

    // ---- block reduce + fenced last-block finish ----
    if (tid == 0) {
        double bce = 0.0, bpt = 0.0;
        #pragma unroll
        for (int i = 0; i < WPB; i++) { bce += s_ce[i]; bpt += s_pt[i]; }
        atomicAdd(&g_ce, bce);
        atomicAdd(&g_pt, bpt);
        __threadfence();
        unsigned old = atomicAdd(&g_count, 1u);
        if (old == gridDim.x - 1) {
            // read through L2 (atomics bypass L1; plain LDG could hit stale L1)
            double CE = atomicAdd(&g_ce, 0.0);
            double PT = atomicAdd(&g_pt, 0.0);
            out[0] = (float)(-CE / (double)B + PT / ((double)B * (double)NCLS));
            // reset for next graph replay
            g_ce = 0.0;
            g_pt = 0.0;
            g_count = 0u;
        }
    }
}

extern "C" void kernel_launch(void* const* d_in, const int* in_sizes, int n_in,
                              void* d_out, int out_size) {
    const float* y_true = (const float*)d_in[0];
    const float* target = (const float*)d_in[1];
    const int B = in_sizes[0] / NCLS;

    ce_pt_kernel<<<BLOCKS, TPB>>>(y_true, target, (float*)d_out, B);
}